// round 14
// baseline (speedup 1.0000x reference)
#include <cuda_runtime.h>
#include <math.h>

#define BATCH 64
#define N 256
#define NT 256
#define INF_F 1e30f
#define FULLM 0xffffffffu
#define ROUNDS 8

// per-batch matched-distance sums (deterministic, no atomics)
__device__ float g_batch_sum[BATCH];

__device__ __forceinline__ float sqrt_approx(float x) {
    float r;
    asm("sqrt.approx.f32 %0, %1;" : "=f"(r) : "f"(x));
    return r;
}

__global__ void __launch_bounds__(NT, 1)
hungarian_kernel(const float* __restrict__ pred,
                 const float* __restrict__ target)
{
    const int b = blockIdx.x;
    const int t = threadIdx.x;      // thread t owns column j = t+1 (1-based)
    const int lane = t & 31;
    const int w = t >> 5;
    const int j = t + 1;

    __shared__ float4 spt[N];                 // pred xyz; .w = row potential u
    __shared__ float4 stgt[N];                // target xyz; .w = live col potential v
    __shared__ int    sp[N + 1];              // row matched to col j (1-based; 0=free)
    __shared__ short  sway[N + 1];            // predecessor column on path (0 = source edge)
    __shared__ short  sargr[N];               // argmin row per column
    __shared__ unsigned char srowm[N];        // row matched flag
    __shared__ short  sunm[N];                // free rows
    __shared__ int    s_nunm;
    __shared__ unsigned sbid[N];              // auction bids (packed margin|tid)
    __shared__ int    swcnt[8];               // per-warp free-row counts
    __shared__ __align__(16) unsigned long long rkey[2][8];  // (exact<<32)|(row<<17)|(src<<8)|col
    __shared__ float  fsum[8];

    // ---- load points ----
    const float* pb = pred   + (size_t)b * N * 3;
    const float* tb = target + (size_t)b * N * 3;
    spt[t] = make_float4(pb[t * 3], pb[t * 3 + 1], pb[t * 3 + 2], 0.0f);
    const float tx = tb[t * 3], ty = tb[t * 3 + 1], tz = tb[t * 3 + 2];
    sp[t] = 0;
    srowm[t] = 0;
    if (t == 0) sp[N] = 0;
    __syncthreads();

    // ---- column reduction on SQUARED distance (sqrt monotonic) ----
    {
        float bd2 = INF_F; int br = 0;
        #pragma unroll 4
        for (int r = 0; r < N; ++r) {
            const float4 p = spt[r];
            const float dx = p.x - tx, dy = p.y - ty, dz = p.z - tz;
            const float d2 = fmaf(dx, dx, fmaf(dy, dy, dz * dz));
            if (d2 < bd2) { bd2 = d2; br = r; }
        }
        sargr[t] = (short)br;
        stgt[t] = make_float4(tx, ty, tz, sqrt_approx(bd2));  // .w = v[j]
    }
    __syncthreads();

    // ---- greedy pre-match on tight edges (t0, serial) ----
    if (t == 0) {
        for (int jj = 1; jj <= N; ++jj) {
            const int r = sargr[jj - 1];
            if (!srowm[r]) { srowm[r] = 1; sp[jj] = r + 1; }
        }
        int cnt = 0;
        for (int r = 0; r < N; ++r)
            if (!srowm[r]) sunm[cnt++] = (short)(r + 1);
        s_nunm = cnt;
    }
    __syncthreads();

    // ======== Jacobi auction rounds (parallel ARR; exact duals kept) ========
    for (int round = 0; round < ROUNDS; ++round) {
        const int cnt = s_nunm;
        if (cnt == 0) break;
        sbid[t] = 0u;
        __syncthreads();

        int irow = 0, bj = 0;
        float margin = 0.0f, u2v = 0.0f;
        unsigned packed = 0u;
        if (t < cnt) {
            irow = sunm[t];
            const float4 pi = spt[irow - 1];
            float u1 = INF_F, u2 = INF_F;
            #pragma unroll 4
            for (int jj = 0; jj < N; ++jj) {
                const float4 g = stgt[jj];
                const float dx = pi.x - g.x, dy = pi.y - g.y, dz = pi.z - g.z;
                const float c = sqrt_approx(fmaf(dx, dx, fmaf(dy, dy, dz * dz))) - g.w;
                if (c < u1) { u2 = u1; u1 = c; bj = jj; }
                else if (c < u2) { u2 = c; }
            }
            margin = u2 - u1;
            u2v = u2;
            packed = (__float_as_uint(margin) & ~0xFFu) | (unsigned)t | 0x80000000u;
            atomicMax(&sbid[bj], packed);
        }
        __syncthreads();

        if (t < cnt && sbid[bj] == packed) {   // deterministic winner
            stgt[bj].w -= margin;
            spt[irow - 1].w = u2v;
            sp[bj + 1] = irow;
        }
        __syncthreads();

        // rebuild free-row list (parallel ballot compaction, fixed row order)
        srowm[t] = 0;
        __syncthreads();
        { const int r = sp[j]; if (r > 0) srowm[r - 1] = 1; }
        __syncthreads();
        {
            const int freef = (srowm[t] == 0) ? 1 : 0;
            const unsigned m = __ballot_sync(FULLM, freef);
            if (lane == 0) swcnt[w] = __popc(m);
            __syncthreads();
            int pre = 0, tot = 0;
            #pragma unroll
            for (int q = 0; q < 8; ++q) {
                if (q < w) pre += swcnt[q];
                tot += swcnt[q];
            }
            if (freef)
                sunm[pre + __popc(m & ((1u << lane) - 1u))] = (short)(t + 1);
            if (t == 0) s_nunm = tot;
        }
        __syncthreads();
    }

    float v = stgt[t].w;                // live v after auction

    // ====== MULTI-SOURCE exact augmenting paths ======
    // One Dijkstra forest seeded from ALL free rows; first settled free column
    // gives an augmenting path for its originating source. Dual updates:
    // settled cols v -= D-d(j), their rows u += D-d(j), ALL free rows u += D.
    // Feasibility + tightness preserved => exact.
    for (;;) {
        const int nunm = s_nunm;
        if (nunm == 0) break;
        const int myi = sp[j];          // my column's matched row (frozen in path)

        // init labels: min over sources of c(i,j) - u[i] - v[j]
        unsigned ekey;
        int      ssrc;                   // originating free row of my label
        {
            float best = INF_F; int bsrc = 1;
            for (int q = 0; q < nunm; ++q) {
                const int i = sunm[q];
                const float4 p = spt[i - 1];
                const float dx = p.x - tx, dy = p.y - ty, dz = p.z - tz;
                const float s = sqrt_approx(fmaf(dx, dx, fmaf(dy, dy, dz * dz)));
                const float cur = s - p.w - v;
                if (cur < best) { best = cur; bsrc = i; }
            }
            ekey = __float_as_uint(fmaxf(best, 0.0f)) | 0x80000000u;
            ssrc = bsrc;
        }
        sway[j] = 0;                     // source edge

        unsigned usedf = 0u;
        float    vv = v;
        float    mshort = 0.0f;
        float    minVal = 0.0f;
        int step = 0;

        for (;;) {
            // REDUX argmin (trunc|lane) + exact min over free columns
            const unsigned kk = ekey | (0u - usedf);
            const unsigned wp = __reduce_min_sync(FULLM, (kk & ~31u) | (unsigned)lane);
            const unsigned we = __reduce_min_sync(FULLM, kk);
            const int buf = step & 1;
            if (lane == (int)(wp & 31u))
                rkey[buf][w] = ((unsigned long long)we << 32)
                             | (unsigned)((myi << 17) | (ssrc << 8) | t);
            __syncthreads();

            const ulonglong2* ra = reinterpret_cast<const ulonglong2*>(rkey[buf]);
            const ulonglong2 a0 = ra[0], a1 = ra[1], a2 = ra[2], a3 = ra[3];
            unsigned long long m0 = a0.x < a0.y ? a0.x : a0.y;
            unsigned long long m1 = a1.x < a1.y ? a1.x : a1.y;
            unsigned long long m2 = a2.x < a2.y ? a2.x : a2.y;
            unsigned long long m3 = a3.x < a3.y ? a3.x : a3.y;
            m0 = m0 < m1 ? m0 : m1;
            m2 = m2 < m3 ? m2 : m3;
            const unsigned long long best = m0 < m2 ? m0 : m2;

            const unsigned lo = (unsigned)best;
            const int bcol = (int)(lo & 0xffu);           // winner thread idx
            const int src1 = (int)((lo >> 8) & 0x1ffu);   // winner's source row
            const int i0n  = (int)((lo >> 17) & 0x1ffu);  // winner col's row (0=free)
            minVal = __uint_as_float(((unsigned)(best >> 32)) & 0x7fffffffu);

            if (i0n == 0) {
                // free column settled: augment path of source src1, distance D=minVal
                if (usedf) {
                    const float d = minVal - mshort;
                    v -= d;
                    spt[myi - 1].w += d;        // settled col's matched row
                }
                if (t < nunm)
                    spt[sunm[t] - 1].w += minVal;   // ALL free rows: u += D
                if (t == 0) {
                    int jj = bcol + 1;
                    for (;;) {
                        const int jn = sway[jj];
                        if (jn == 0) { sp[jj] = src1; break; }
                        sp[jj] = sp[jn];
                        jj = jn;
                    }
                }
                __syncthreads();        // sunm reads done; sp/u published
                if (t == 0) {           // remove matched source from free list
                    int c2 = 0;
                    for (int q = 0; q < nunm; ++q) {
                        const short r = sunm[q];
                        if ((int)r != src1) sunm[c2++] = r;
                    }
                    s_nunm = c2;
                }
                __syncthreads();
                break;
            }

            // expand tree from (row i0n, column bcol+1)
            const int j0 = bcol + 1;
            if (j0 == j) {              // my column settled: freeze, mark
                usedf = 1u;
                mshort = minVal;
                vv = -INF_F;
            }
            const float4 p = spt[i0n - 1];      // xyz + u, LDS.128 broadcast
            const float dx = p.x - tx, dy = p.y - ty, dz = p.z - tz;
            const float s  = sqrt_approx(fmaf(dx, dx, fmaf(dy, dy, dz * dz)));
            const float cur = fmaxf((minVal - p.w - vv) + s, 0.0f);  // used: +INF
            const unsigned ck = __float_as_uint(cur) | 0x80000000u;
            if (ck < ekey) {            // used cols: INF key never passes
                ekey = ck;
                sway[j] = (short)j0;
                ssrc = src1;            // inherit winner's source
            }
            ++step;
        }
    }

    // ---- matched distance for my column (exact sqrt) ----
    const int r = sp[j] - 1;
    const float4 p = spt[r];
    const float dx = p.x - tx, dy = p.y - ty, dz = p.z - tz;
    float md = sqrtf(fmaf(dx, dx, fmaf(dy, dy, dz * dz)));

    #pragma unroll
    for (int o = 16; o > 0; o >>= 1)
        md += __shfl_down_sync(FULLM, md, o);
    if (lane == 0) fsum[w] = md;
    __syncthreads();
    if (t == 0) {
        float s = 0.0f;
        #pragma unroll
        for (int q = 0; q < 8; ++q) s += fsum[q];
        g_batch_sum[b] = s;
    }
}

__global__ void finalize_kernel(float* __restrict__ out)
{
    double s = 0.0;
    #pragma unroll
    for (int b = 0; b < BATCH; ++b) s += (double)g_batch_sum[b];
    out[0] = (float)(s / (double)BATCH);
}

extern "C" void kernel_launch(void* const* d_in, const int* in_sizes, int n_in,
                              void* d_out, int out_size)
{
    const float* pred   = (const float*)d_in[0];
    const float* target = (const float*)d_in[1];
    float* out = (float*)d_out;

    hungarian_kernel<<<BATCH, NT>>>(pred, target);
    finalize_kernel<<<1, 1>>>(out);
}

// round 15
// speedup vs baseline: 1.7669x; 1.7669x over previous
#include <cuda_runtime.h>
#include <math.h>

#define BATCH 64
#define N 256
#define NT 256
#define INF_F 1e30f
#define FULLM 0xffffffffu
#define ROUNDS 14

// per-batch matched-distance sums (deterministic, no atomics)
__device__ float g_batch_sum[BATCH];

__device__ __forceinline__ float sqrt_approx(float x) {
    float r;
    asm("sqrt.approx.f32 %0, %1;" : "=f"(r) : "f"(x));
    return r;
}

__global__ void __launch_bounds__(NT, 1)
hungarian_kernel(const float* __restrict__ pred,
                 const float* __restrict__ target)
{
    const int b = blockIdx.x;
    const int t = threadIdx.x;      // thread t owns column j = t+1 (1-based)
    const int lane = t & 31;
    const int w = t >> 5;
    const int j = t + 1;

    __shared__ float4 spt[N];                 // pred xyz; .w = row potential u
    __shared__ float4 stgt[N];                // target xyz; .w = live col potential v
    __shared__ int    sp[N + 1];              // row matched to col j (1-based; 0=free)
    __shared__ short  sway[N + 1];            // predecessor column on path
    __shared__ short  sargr[N];               // argmin row per column
    __shared__ unsigned char srowm[N];        // row matched flag
    __shared__ short  sunm[N];                // free rows
    __shared__ int    s_nunm;
    __shared__ unsigned sbid[N];              // auction bids (packed margin|tid)
    __shared__ int    swcnt[8];               // per-warp free-row counts
    __shared__ __align__(16) unsigned long long rkey[2][8];  // (exactmin<<32)|(row<<8)|col
    __shared__ float  fsum[8];

    // ---- load points ----
    const float* pb = pred   + (size_t)b * N * 3;
    const float* tb = target + (size_t)b * N * 3;
    spt[t] = make_float4(pb[t * 3], pb[t * 3 + 1], pb[t * 3 + 2], 0.0f);
    const float tx = tb[t * 3], ty = tb[t * 3 + 1], tz = tb[t * 3 + 2];
    sp[t] = 0;
    srowm[t] = 0;
    if (t == 0) sp[N] = 0;
    __syncthreads();

    // ---- column reduction on SQUARED distance (sqrt monotonic) ----
    {
        float bd2 = INF_F; int br = 0;
        #pragma unroll 4
        for (int r = 0; r < N; ++r) {
            const float4 p = spt[r];
            const float dx = p.x - tx, dy = p.y - ty, dz = p.z - tz;
            const float d2 = fmaf(dx, dx, fmaf(dy, dy, dz * dz));
            if (d2 < bd2) { bd2 = d2; br = r; }
        }
        sargr[t] = (short)br;
        stgt[t] = make_float4(tx, ty, tz, sqrt_approx(bd2));  // .w = v[j]
    }
    __syncthreads();

    // ---- greedy pre-match on tight edges (t0, serial) ----
    if (t == 0) {
        for (int jj = 1; jj <= N; ++jj) {
            const int r = sargr[jj - 1];
            if (!srowm[r]) { srowm[r] = 1; sp[jj] = r + 1; }
        }
        int cnt = 0;
        for (int r = 0; r < N; ++r)
            if (!srowm[r]) sunm[cnt++] = (short)(r + 1);
        s_nunm = cnt;
    }
    __syncthreads();

    // ======== Jacobi auction rounds (parallel ARR; exact duals kept) ========
    for (int round = 0; round < ROUNDS; ++round) {
        const int cnt = s_nunm;
        if (cnt == 0) break;
        sbid[t] = 0u;
        __syncthreads();

        int irow = 0, bj = 0;
        float margin = 0.0f, u2v = 0.0f;
        unsigned packed = 0u;
        if (t < cnt) {
            irow = sunm[t];
            const float4 pi = spt[irow - 1];
            float u1 = INF_F, u2 = INF_F;
            #pragma unroll 4
            for (int jj = 0; jj < N; ++jj) {
                const float4 g = stgt[jj];
                const float dx = pi.x - g.x, dy = pi.y - g.y, dz = pi.z - g.z;
                const float c = sqrt_approx(fmaf(dx, dx, fmaf(dy, dy, dz * dz))) - g.w;
                if (c < u1) { u2 = u1; u1 = c; bj = jj; }
                else if (c < u2) { u2 = c; }
            }
            margin = u2 - u1;            // >= 0, finite
            u2v = u2;
            packed = (__float_as_uint(margin) & ~0xFFu) | (unsigned)t | 0x80000000u;
            atomicMax(&sbid[bj], packed);
        }
        __syncthreads();

        if (t < cnt && sbid[bj] == packed) {   // deterministic winner
            stgt[bj].w -= margin;              // unique column writer
            spt[irow - 1].w = u2v;             // unique row writer
            sp[bj + 1] = irow;                 // steal / take column
        }
        __syncthreads();

        // rebuild free-row list (parallel ballot compaction, fixed row order)
        srowm[t] = 0;
        __syncthreads();
        { const int r = sp[j]; if (r > 0) srowm[r - 1] = 1; }
        __syncthreads();
        {
            const int freef = (srowm[t] == 0) ? 1 : 0;   // row t+1 free?
            const unsigned m = __ballot_sync(FULLM, freef);
            if (lane == 0) swcnt[w] = __popc(m);
            __syncthreads();
            int pre = 0, tot = 0;
            #pragma unroll
            for (int q = 0; q < 8; ++q) {
                if (q < w) pre += swcnt[q];
                tot += swcnt[q];
            }
            if (freef)
                sunm[pre + __popc(m & ((1u << lane) - 1u))] = (short)(t + 1);
            if (t == 0) s_nunm = tot;
        }
        __syncthreads();
    }

    // ======== JV reduction transfer (parallel; exact duals kept) ========
    // For each matched row i on column j1: µ2 = min_{j≠j1}(c(i,j)-v[j]);
    // v[j1] = c(i,j1) - µ2 (only decreases), u[i] = µ2. Matched edge stays
    // tight, feasibility preserved => Dijkstra below remains exact, but
    // matched columns carry their true second-best slack => smaller trees.
    {
        const int i = sp[j];             // row matched to my column (0 if free)
        float mu2 = INF_F, dii = 0.0f;
        if (i > 0) {
            const float4 pi = spt[i - 1];
            #pragma unroll 4
            for (int jj = 0; jj < N; ++jj) {
                const float4 g = stgt[jj];
                const float dx = pi.x - g.x, dy = pi.y - g.y, dz = pi.z - g.z;
                const float d = sqrt_approx(fmaf(dx, dx, fmaf(dy, dy, dz * dz)));
                if (jj == t) dii = d;
                else         mu2 = fminf(mu2, d - g.w);
            }
        }
        __syncthreads();                 // all v reads complete
        if (i > 0) {
            stgt[t].w = dii - mu2;       // unique column writer
            spt[i - 1].w = mu2;          // unique row writer
        }
        __syncthreads();
    }

    float v = stgt[t].w;                // live v after auction + transfer
    const int nunm = s_nunm;

    // ====== exact augmenting paths (Dijkstra, deferred dual updates) ======
    for (int ii = 0; ii < nunm; ++ii) {
        const int istart = sunm[ii];
        const int myi = sp[j];          // my column's matched row (frozen during path)
        unsigned ekey  = 0xfffffff0u;   // fmap(shortest); frozen once used
        unsigned usedf = 0u;
        float    vv = v;                // -INF marks used (cost -> +INF, no updates)
        float    mshort = 0.0f;
        float    minVal = 0.0f;
        int i0 = istart, j0 = 0, step = 0;

        for (;;) {
            if (j0 == j) {               // my column settled: freeze, mark
                usedf = 1u;
                mshort = minVal;
                vv = -INF_F;
            }

            const float4 p = spt[i0 - 1];          // xyz + u[i0], LDS.128 bcast
            const float dx = p.x - tx, dy = p.y - ty, dz = p.z - tz;
            const float s  = sqrt_approx(fmaf(dx, dx, fmaf(dy, dy, dz * dz)));
            const float cur = fmaxf((minVal - p.w - vv) + s, 0.0f);  // used: +INF
            const unsigned ck = __float_as_uint(cur) | 0x80000000u;
            if (ck < ekey) {             // used cols: INF key never passes
                ekey = ck;
                sway[j] = (short)j0;
            }

            // masked key; REDUX argmin (trunc|lane) + exact min value
            const unsigned kk = ekey | (0u - usedf);
            const unsigned wp = __reduce_min_sync(FULLM, (kk & ~31u) | (unsigned)lane);
            const unsigned we = __reduce_min_sync(FULLM, kk);
            const int buf = step & 1;
            if (lane == (int)(wp & 31u))         // warp winner publishes its row+col
                rkey[buf][w] = ((unsigned long long)we << 32)
                             | (unsigned)((myi << 8) | t);
            __syncthreads();

            // block combine: 4x LDS.128, u64 min tree
            const ulonglong2* ra = reinterpret_cast<const ulonglong2*>(rkey[buf]);
            const ulonglong2 a0 = ra[0], a1 = ra[1], a2 = ra[2], a3 = ra[3];
            unsigned long long m0 = a0.x < a0.y ? a0.x : a0.y;
            unsigned long long m1 = a1.x < a1.y ? a1.x : a1.y;
            unsigned long long m2 = a2.x < a2.y ? a2.x : a2.y;
            unsigned long long m3 = a3.x < a3.y ? a3.x : a3.y;
            m0 = m0 < m1 ? m0 : m1;
            m2 = m2 < m3 ? m2 : m3;
            const unsigned long long best = m0 < m2 ? m0 : m2;

            const unsigned lo = (unsigned)best;
            const int bcol = (int)(lo & 0xffu);          // winner thread idx
            const int i0n  = (int)((lo >> 8) & 0x1ffu);  // sp of winner col (0=free)
            minVal = __uint_as_float(((unsigned)(best >> 32)) & 0x7fffffffu);

            if (i0n == 0) {
                // sink column bcol+1 is free: finish path
                if (usedf) {
                    const float d = minVal - mshort;
                    v -= d;
                    spt[myi - 1].w += d;     // distinct rows per used col: no conflict
                }
                if (t == 0) {
                    spt[istart - 1].w += minVal;
                    sp[0] = istart;          // terminus picks up the free row
                    int jj = bcol + 1;
                    while (jj) {
                        const int jn = sway[jj];
                        sp[jj] = sp[jn];
                        jj = jn;
                    }
                }
                __syncthreads();             // publish sp/u for next path
                break;
            }
            j0 = bcol + 1;
            i0 = i0n;
            ++step;
        }
    }

    // ---- matched distance for my column (exact sqrt) ----
    const int r = sp[j] - 1;
    const float4 p = spt[r];
    const float dx = p.x - tx, dy = p.y - ty, dz = p.z - tz;
    float md = sqrtf(fmaf(dx, dx, fmaf(dy, dy, dz * dz)));

    #pragma unroll
    for (int o = 16; o > 0; o >>= 1)
        md += __shfl_down_sync(FULLM, md, o);
    if (lane == 0) fsum[w] = md;
    __syncthreads();
    if (t == 0) {
        float s = 0.0f;
        #pragma unroll
        for (int q = 0; q < 8; ++q) s += fsum[q];
        g_batch_sum[b] = s;
    }
}

__global__ void finalize_kernel(float* __restrict__ out)
{
    double s = 0.0;
    #pragma unroll
    for (int b = 0; b < BATCH; ++b) s += (double)g_batch_sum[b];
    out[0] = (float)(s / (double)BATCH);
}

extern "C" void kernel_launch(void* const* d_in, const int* in_sizes, int n_in,
                              void* d_out, int out_size)
{
    const float* pred   = (const float*)d_in[0];
    const float* target = (const float*)d_in[1];
    float* out = (float*)d_out;

    hungarian_kernel<<<BATCH, NT>>>(pred, target);
    finalize_kernel<<<1, 1>>>(out);
}